// round 13
// baseline (speedup 1.0000x reference)
#include <cuda_runtime.h>
#include <cstdint>

#define E_   1024
#define L_   24
#define H_   4096
#define V_   50277
#define TPB  256
#define WPB  8          // warps per block
#define RABB 32         // blocks producing the WKV/rab vector

struct Params {
    const int*   ctx;
    const float* xx_att; const float* aa_att; const float* bb_att;
    const float* pp_att; const float* xx_ffn;
    const float* emb_w;  const float* head_w;
    const float* ln0_w;  const float* ln0_b;
    const float* ln1_w;  const float* ln1_b;
    const float* ln2_w;  const float* ln2_b;
    const float* lno_w;  const float* lno_b;
    const float* mix_k;  const float* mix_v;  const float* mix_r;
    const float* tfirst; const float* tdecay;
    const float* Wr; const float* Wk; const float* Wv; const float* Wo;
    const float* fmk; const float* fmr;
    const float* Fr;  const float* Fk;  const float* Fv;
    float* out;
    unsigned nb;
};

// Cross-phase scratch (device globals: no allocations allowed)
__device__ __align__(16) float g_x[E_];
__device__ __align__(16) float g_kk[E_];
__device__ __align__(16) float g_vv[E_];
__device__ __align__(16) float g_rpre[E_];
__device__ __align__(16) float g_rab[E_];
__device__ __align__(16) float g_kf[H_];
__device__ __align__(16) float g_rfpre[E_];

// Monotonic barrier state (never reset across calls; targets are relative)
__device__ unsigned g_bar_cnt;
__device__ unsigned g_bar_gen;
__device__ unsigned g_rab_cnt;
__device__ unsigned g_rab_gen;

__device__ __forceinline__ float warp_red(float v) {
    #pragma unroll
    for (int o = 16; o > 0; o >>= 1) v += __shfl_down_sync(0xffffffffu, v, o);
    return v;
}

__device__ __forceinline__ float block_sum(float v, float* s_red) {
    int lane = threadIdx.x & 31, warp = threadIdx.x >> 5;
    v = warp_red(v);
    if (lane == 0) s_red[warp] = v;
    __syncthreads();
    if (warp == 0) {
        float t = (lane < WPB) ? s_red[lane] : 0.0f;
        #pragma unroll
        for (int o = 4; o > 0; o >>= 1) t += __shfl_down_sync(0xffffffffu, t, o);
        if (lane == 0) s_red[32] = t;
    }
    __syncthreads();
    return s_red[32];
}

// Grid-wide barrier: all threads fence, tid0 arrives; last arriver resets the
// counter and bumps the generation; others spin on the generation.
__device__ __forceinline__ void gsync(unsigned nb, unsigned target) {
    __threadfence();
    __syncthreads();
    if (threadIdx.x == 0) {
        if (atomicAdd(&g_bar_cnt, 1u) == nb - 1u) {
            g_bar_cnt = 0u;
            __threadfence();
            atomicAdd(&g_bar_gen, 1u);
        } else {
            while ((int)(*(volatile unsigned*)&g_bar_gen - target) < 0) __nanosleep(64);
        }
        __threadfence();
    }
    __syncthreads();
}

// LayerNorm of a distributed vector: thread t holds elements [4t,4t+4).
__device__ __forceinline__ float4 ln_vec(float4 v, const float* w, const float* b,
                                         float* s_red) {
    int tid = threadIdx.x;
    float s = block_sum(v.x + v.y + v.z + v.w, s_red);
    float mean = s * (1.0f / E_);
    float4 c = make_float4(v.x - mean, v.y - mean, v.z - mean, v.w - mean);
    float ss = block_sum(c.x*c.x + c.y*c.y + c.z*c.z + c.w*c.w, s_red);
    float rstd = rsqrtf(ss * (1.0f / E_) + 1e-5f);
    float4 w4 = ((const float4*)w)[tid];
    float4 b4 = ((const float4*)b)[tid];
    return make_float4(c.x*rstd*w4.x + b4.x, c.y*rstd*w4.y + b4.y,
                       c.z*rstd*w4.z + b4.z, c.w*rstd*w4.w + b4.w);
}

__device__ __forceinline__ float4 mix4(float4 xn, float4 sx, float4 m) {
    return make_float4(xn.x*m.x + sx.x*(1.0f-m.x),
                       xn.y*m.y + sx.y*(1.0f-m.y),
                       xn.z*m.z + sx.z*(1.0f-m.z),
                       xn.w*m.w + sx.w*(1.0f-m.w));
}

// Warp dot of a 1024-long weight row (streamed, .cs) with an SMEM vector.
__device__ __forceinline__ float dot_row_E(const float* wrow, const float* vec, int lane) {
    const float4* w4 = (const float4*)wrow;
    const float4* v4 = (const float4*)vec;
    float acc = 0.0f;
    #pragma unroll
    for (int j = lane; j < E_/4; j += 32) {
        float4 a = __ldcs(w4 + j);
        float4 b = v4[j];
        acc += a.x*b.x + a.y*b.y + a.z*b.z + a.w*b.w;
    }
    return warp_red(acc);
}

// Warp dot of a 4096-long weight row with an SMEM vector.
__device__ __forceinline__ float dot_row_H(const float* wrow, const float* vec, int lane) {
    const float4* w4 = (const float4*)wrow;
    const float4* v4 = (const float4*)vec;
    float acc = 0.0f;
    #pragma unroll 8
    for (int j = lane; j < H_/4; j += 32) {
        float4 a = __ldcs(w4 + j);
        float4 b = v4[j];
        acc += a.x*b.x + a.y*b.y + a.z*b.z + a.w*b.w;
    }
    return warp_red(acc);
}

__global__ void __launch_bounds__(TPB) rwkv_kernel(Params p) {
    __shared__ float s_buf[H_];   // 16KB: phase-dependent vector cache
    __shared__ float s_red[33];

    const unsigned nb   = p.nb;
    const unsigned bid  = blockIdx.x;
    const int tid  = threadIdx.x;
    const int lane = tid & 31;
    const int warp = tid >> 5;
    const unsigned gwarp = bid * WPB + (unsigned)warp;
    const unsigned nwarp = nb * WPB;

    // Barrier bases sampled before any arrival (stable: previous launch done).
    unsigned bar_t = *(volatile unsigned*)&g_bar_gen;
    unsigned rab_t = *(volatile unsigned*)&g_rab_gen;

    const unsigned O_XX = V_;
    const unsigned O_AA = V_ + 1u*L_*E_;
    const unsigned O_BB = V_ + 2u*L_*E_;
    const unsigned O_PP = V_ + 3u*L_*E_;
    const unsigned O_XF = V_ + 4u*L_*E_;
    const unsigned O_DA = V_ + 5u*L_*E_;
    const unsigned O_DB = V_ + 6u*L_*E_;

    // ---- embedding: x0 = LN(emb_w[ctx], ln0) ----
    if (bid == 0) {
        int tok = p.ctx[0];
        float4 ev = __ldcs(((const float4*)(p.emb_w + (size_t)tok * E_)) + tid);
        float4 x0 = ln_vec(ev, p.ln0_w, p.ln0_b, s_red);
        ((float4*)g_x)[tid] = x0;
    }
    bar_t++; gsync(nb, bar_t);

    for (int l = 0; l < L_; ++l) {
        const unsigned le = (unsigned)l * E_;

        // ================= phase 1: LN1 + mixes + r/k/v matvecs =============
        {
            float4 xv = __ldcg(((const float4*)g_x) + tid);
            float4 xn = ln_vec(xv, p.ln1_w + le, p.ln1_b + le, s_red);
            float4 sx = ((const float4*)(p.xx_att + le))[tid];
            float4 mr = ((const float4*)(p.mix_r + le))[tid];
            float4 mk = ((const float4*)(p.mix_k + le))[tid];
            float4 mv = ((const float4*)(p.mix_v + le))[tid];
            ((float4*)(s_buf + 0   ))[tid] = mix4(xn, sx, mr);   // xr
            ((float4*)(s_buf + E_  ))[tid] = mix4(xn, sx, mk);   // xk
            ((float4*)(s_buf + 2*E_))[tid] = mix4(xn, sx, mv);   // xv
            if (bid == 0) {
                float* o = p.out + O_XX + le + tid*4;
                o[0]=xn.x; o[1]=xn.y; o[2]=xn.z; o[3]=xn.w;
            }
            __syncthreads();
            for (unsigned idx = gwarp; idx < 3u*E_; idx += nwarp) {
                unsigned m   = idx >> 10;
                unsigned row = idx & (E_ - 1u);
                const float* wmat = (m == 0u) ? p.Wr : (m == 1u) ? p.Wk : p.Wv;
                float acc = dot_row_E(wmat + ((size_t)le + row) * E_,
                                      s_buf + m * E_, lane);
                if (lane == 0) {
                    if (m == 0u) {
                        g_rpre[row] = acc;
                        p.out[O_DA + le + row] = acc;
                        p.out[O_DB + le + row] = 1.0f / (1.0f + expf(-acc));
                    } else if (m == 1u) g_kk[row] = acc;
                    else                g_vv[row] = acc;
                }
            }
        }
        bar_t++; gsync(nb, bar_t);

        // ===== WKV elementwise (distributed producers, 32 elems each) =======
        if (bid < RABB && warp == 0) {
            int j  = (int)bid * 32 + lane;
            float kk = __ldcg(g_kk + j), vv = __ldcg(g_vv + j);
            float aa = p.aa_att[le + j], bb = p.bb_att[le + j], pp = p.pp_att[le + j];
            float tf = p.tfirst[le + j], td = p.tdecay[le + j];
            float ww = tf + kk;
            float q  = fmaxf(pp, ww);
            float e1 = expf(pp - q), e2 = expf(ww - q);
            float a  = e1 * aa + e2 * vv;
            float b  = e1 * bb + e2;
            float r  = 1.0f / (1.0f + expf(-__ldcg(g_rpre + j)));
            g_rab[j] = r * a / b;
            float ww2 = pp + td;
            float q2  = fmaxf(ww2, kk);
            float e1b = expf(ww2 - q2), e2b = expf(kk - q2);
            p.out[O_AA + le + j] = e1b * aa + e2b * vv;
            p.out[O_BB + le + j] = e1b * bb + e2b;
            p.out[O_PP + le + j] = q2;
            __threadfence();
            if (lane == 0) {
                if (atomicAdd(&g_rab_cnt, 1u) == RABB - 1u) {
                    g_rab_cnt = 0u;
                    __threadfence();
                    atomicAdd(&g_rab_gen, 1u);
                }
            }
        }
        rab_t++;
        if (tid == 0) {
            while ((int)(*(volatile unsigned*)&g_rab_gen - rab_t) < 0) __nanosleep(32);
            __threadfence();
        }
        __syncthreads();

        // ================= phase 2: x += Wo @ rab ===========================
        ((float4*)s_buf)[tid] = __ldcg(((const float4*)g_rab) + tid);
        __syncthreads();
        for (unsigned row = gwarp; row < E_; row += nwarp) {
            float acc = dot_row_E(p.Wo + ((size_t)le + row) * E_, s_buf, lane);
            if (lane == 0) g_x[row] = __ldcg(g_x + row) + acc;
        }
        bar_t++; gsync(nb, bar_t);

        // ================= phase 3: LN2 + FFN r/k matvecs ===================
        {
            float4 xv  = __ldcg(((const float4*)g_x) + tid);
            float4 xn2 = ln_vec(xv, p.ln2_w + le, p.ln2_b + le, s_red);
            float4 sxf = ((const float4*)(p.xx_ffn + le))[tid];
            float4 fk  = ((const float4*)(p.fmk + le))[tid];
            float4 fr  = ((const float4*)(p.fmr + le))[tid];
            ((float4*)(s_buf + 0 ))[tid] = mix4(xn2, sxf, fk);   // fxk
            ((float4*)(s_buf + E_))[tid] = mix4(xn2, sxf, fr);   // fxr
            if (bid == 0) {
                float* o = p.out + O_XF + le + tid*4;
                o[0]=xn2.x; o[1]=xn2.y; o[2]=xn2.z; o[3]=xn2.w;
            }
            __syncthreads();
            for (unsigned idx = gwarp; idx < (unsigned)(H_ + E_); idx += nwarp) {
                if (idx < (unsigned)H_) {
                    float acc = dot_row_E(p.Fk + ((size_t)l * H_ + idx) * E_,
                                          s_buf, lane);
                    if (lane == 0) { float t = fmaxf(acc, 0.0f); g_kf[idx] = t * t; }
                } else {
                    unsigned row = idx - (unsigned)H_;
                    float acc = dot_row_E(p.Fr + ((size_t)le + row) * E_,
                                          s_buf + E_, lane);
                    if (lane == 0) g_rfpre[row] = acc;
                }
            }
        }
        bar_t++; gsync(nb, bar_t);

        // ================= phase 4: x += sigmoid(rf) * (Fv @ kf) ============
        #pragma unroll
        for (int i = tid; i < H_/4; i += TPB)
            ((float4*)s_buf)[i] = __ldcg(((const float4*)g_kf) + i);
        __syncthreads();
        for (unsigned row = gwarp; row < E_; row += nwarp) {
            float acc = dot_row_H(p.Fv + ((size_t)le + row) * H_, s_buf, lane);
            if (lane == 0) {
                float rf = 1.0f / (1.0f + expf(-__ldcg(g_rfpre + row)));
                g_x[row] = __ldcg(g_x + row) + rf * acc;
            }
        }
        bar_t++; gsync(nb, bar_t);
    }

    // ================= head: logits = head_w @ LN(x, lno) ===================
    {
        float4 xv = __ldcg(((const float4*)g_x) + tid);
        float4 xo = ln_vec(xv, p.lno_w, p.lno_b, s_red);
        ((float4*)s_buf)[tid] = xo;
        __syncthreads();
        for (unsigned row = gwarp; row < (unsigned)V_; row += nwarp) {
            float acc = dot_row_E(p.head_w + (size_t)row * E_, s_buf, lane);
            if (lane == 0) p.out[row] = acc;
        }
    }
}

extern "C" void kernel_launch(void* const* d_in, const int* in_sizes, int n_in,
                              void* d_out, int out_size) {
    (void)in_sizes; (void)n_in; (void)out_size;
    Params p;
    p.ctx    = (const int*)  d_in[0];
    p.xx_att = (const float*)d_in[1];
    p.aa_att = (const float*)d_in[2];
    p.bb_att = (const float*)d_in[3];
    p.pp_att = (const float*)d_in[4];
    p.xx_ffn = (const float*)d_in[5];
    p.emb_w  = (const float*)d_in[6];
    p.head_w = (const float*)d_in[7];
    p.ln0_w  = (const float*)d_in[8];
    p.ln0_b  = (const float*)d_in[9];
    p.ln1_w  = (const float*)d_in[10];
    p.ln1_b  = (const float*)d_in[11];
    p.ln2_w  = (const float*)d_in[12];
    p.ln2_b  = (const float*)d_in[13];
    p.lno_w  = (const float*)d_in[14];
    p.lno_b  = (const float*)d_in[15];
    p.mix_k  = (const float*)d_in[16];
    p.mix_v  = (const float*)d_in[17];
    p.mix_r  = (const float*)d_in[18];
    p.tfirst = (const float*)d_in[19];
    p.tdecay = (const float*)d_in[20];
    p.Wr     = (const float*)d_in[21];
    p.Wk     = (const float*)d_in[22];
    p.Wv     = (const float*)d_in[23];
    p.Wo     = (const float*)d_in[24];
    p.fmk    = (const float*)d_in[25];
    p.fmr    = (const float*)d_in[26];
    p.Fr     = (const float*)d_in[27];
    p.Fk     = (const float*)d_in[28];
    p.Fv     = (const float*)d_in[29];
    p.out    = (float*)d_out;

    int dev = 0;
    cudaGetDevice(&dev);
    int sms = 0;
    cudaDeviceGetAttribute(&sms, cudaDevAttrMultiProcessorCount, dev);
    int bpm = 0;
    cudaOccupancyMaxActiveBlocksPerMultiprocessor(&bpm, rwkv_kernel, TPB, 0);
    if (bpm < 1) bpm = 1;
    if (bpm > 2) bpm = 2;          // cap: limits redundancy + barrier traffic
    unsigned nb = (unsigned)(sms * bpm);
    p.nb = nb;

    rwkv_kernel<<<nb, TPB>>>(p);
}

// round 14
// speedup vs baseline: 1.0343x; 1.0343x over previous
#include <cuda_runtime.h>
#include <cstdint>

#define E_   1024
#define L_   24
#define H_   4096
#define V_   50277
#define TPB  256
#define WPB  8          // warps per block
#define RABB 32         // blocks producing the WKV/rab vector

struct Params {
    const int*   ctx;
    const float* xx_att; const float* aa_att; const float* bb_att;
    const float* pp_att; const float* xx_ffn;
    const float* emb_w;  const float* head_w;
    const float* ln0_w;  const float* ln0_b;
    const float* ln1_w;  const float* ln1_b;
    const float* ln2_w;  const float* ln2_b;
    const float* lno_w;  const float* lno_b;
    const float* mix_k;  const float* mix_v;  const float* mix_r;
    const float* tfirst; const float* tdecay;
    const float* Wr; const float* Wk; const float* Wv; const float* Wo;
    const float* fmk; const float* fmr;
    const float* Fr;  const float* Fk;  const float* Fv;
    float* out;
    unsigned nb;
};

// Cross-phase scratch (device globals: no allocations allowed)
__device__ __align__(16) float g_x[E_];
__device__ __align__(16) float g_kk[E_];
__device__ __align__(16) float g_vv[E_];
__device__ __align__(16) float g_rpre[E_];
__device__ __align__(16) float g_rab[E_];
__device__ __align__(16) float g_kf[H_];
__device__ __align__(16) float g_rfpre[E_];

// Monotonic barrier state (never reset across calls; targets are relative)
__device__ unsigned g_bar_cnt;
__device__ unsigned g_bar_gen;
__device__ unsigned g_rab_cnt;
__device__ unsigned g_rab_gen;

__device__ __forceinline__ float warp_red(float v) {
    #pragma unroll
    for (int o = 16; o > 0; o >>= 1) v += __shfl_down_sync(0xffffffffu, v, o);
    return v;
}

__device__ __forceinline__ float block_sum(float v, float* s_red) {
    int lane = threadIdx.x & 31, warp = threadIdx.x >> 5;
    v = warp_red(v);
    if (lane == 0) s_red[warp] = v;
    __syncthreads();
    if (warp == 0) {
        float t = (lane < WPB) ? s_red[lane] : 0.0f;
        #pragma unroll
        for (int o = 4; o > 0; o >>= 1) t += __shfl_down_sync(0xffffffffu, t, o);
        if (lane == 0) s_red[32] = t;
    }
    __syncthreads();
    return s_red[32];
}

// Grid-wide barrier: all threads fence, tid0 arrives; last arriver resets the
// counter and bumps the generation; others spin on the generation.
__device__ __forceinline__ void gsync(unsigned nb, unsigned target) {
    __threadfence();
    __syncthreads();
    if (threadIdx.x == 0) {
        if (atomicAdd(&g_bar_cnt, 1u) == nb - 1u) {
            g_bar_cnt = 0u;
            __threadfence();
            atomicAdd(&g_bar_gen, 1u);
        } else {
            while ((int)(*(volatile unsigned*)&g_bar_gen - target) < 0) __nanosleep(64);
        }
        __threadfence();
    }
    __syncthreads();
}

// LayerNorm of a distributed vector: thread t holds elements [4t,4t+4).
__device__ __forceinline__ float4 ln_vec(float4 v, const float* w, const float* b,
                                         float* s_red) {
    int tid = threadIdx.x;
    float s = block_sum(v.x + v.y + v.z + v.w, s_red);
    float mean = s * (1.0f / E_);
    float4 c = make_float4(v.x - mean, v.y - mean, v.z - mean, v.w - mean);
    float ss = block_sum(c.x*c.x + c.y*c.y + c.z*c.z + c.w*c.w, s_red);
    float rstd = rsqrtf(ss * (1.0f / E_) + 1e-5f);
    float4 w4 = ((const float4*)w)[tid];
    float4 b4 = ((const float4*)b)[tid];
    return make_float4(c.x*rstd*w4.x + b4.x, c.y*rstd*w4.y + b4.y,
                       c.z*rstd*w4.z + b4.z, c.w*rstd*w4.w + b4.w);
}

__device__ __forceinline__ float4 mix4(float4 xn, float4 sx, float4 m) {
    return make_float4(xn.x*m.x + sx.x*(1.0f-m.x),
                       xn.y*m.y + sx.y*(1.0f-m.y),
                       xn.z*m.z + sx.z*(1.0f-m.z),
                       xn.w*m.w + sx.w*(1.0f-m.w));
}

// Warp dot of a 1024-long weight row (streamed, .cs) with an SMEM vector.
__device__ __forceinline__ float dot_row_E(const float* wrow, const float* vec, int lane) {
    const float4* w4 = (const float4*)wrow;
    const float4* v4 = (const float4*)vec;
    float acc = 0.0f;
    #pragma unroll
    for (int j = lane; j < E_/4; j += 32) {
        float4 a = __ldcs(w4 + j);
        float4 b = v4[j];
        acc += a.x*b.x + a.y*b.y + a.z*b.z + a.w*b.w;
    }
    return warp_red(acc);
}

// Warp dot of a 4096-long weight row with an SMEM vector.
__device__ __forceinline__ float dot_row_H(const float* wrow, const float* vec, int lane) {
    const float4* w4 = (const float4*)wrow;
    const float4* v4 = (const float4*)vec;
    float acc = 0.0f;
    #pragma unroll 8
    for (int j = lane; j < H_/4; j += 32) {
        float4 a = __ldcs(w4 + j);
        float4 b = v4[j];
        acc += a.x*b.x + a.y*b.y + a.z*b.z + a.w*b.w;
    }
    return warp_red(acc);
}

__global__ void __launch_bounds__(TPB) rwkv_kernel(Params p) {
    __shared__ float s_buf[H_];   // 16KB: phase-dependent vector cache
    __shared__ float s_red[33];

    const unsigned nb   = p.nb;
    const unsigned bid  = blockIdx.x;
    const int tid  = threadIdx.x;
    const int lane = tid & 31;
    const int warp = tid >> 5;
    const unsigned gwarp = bid * WPB + (unsigned)warp;
    const unsigned nwarp = nb * WPB;

    // Barrier bases sampled before any arrival (stable: previous launch done).
    unsigned bar_t = *(volatile unsigned*)&g_bar_gen;
    unsigned rab_t = *(volatile unsigned*)&g_rab_gen;

    const unsigned O_XX = V_;
    const unsigned O_AA = V_ + 1u*L_*E_;
    const unsigned O_BB = V_ + 2u*L_*E_;
    const unsigned O_PP = V_ + 3u*L_*E_;
    const unsigned O_XF = V_ + 4u*L_*E_;
    const unsigned O_DA = V_ + 5u*L_*E_;
    const unsigned O_DB = V_ + 6u*L_*E_;

    // ---- embedding: x0 = LN(emb_w[ctx], ln0) ----
    if (bid == 0) {
        int tok = p.ctx[0];
        float4 ev = __ldcs(((const float4*)(p.emb_w + (size_t)tok * E_)) + tid);
        float4 x0 = ln_vec(ev, p.ln0_w, p.ln0_b, s_red);
        ((float4*)g_x)[tid] = x0;
    }
    bar_t++; gsync(nb, bar_t);

    for (int l = 0; l < L_; ++l) {
        const unsigned le = (unsigned)l * E_;

        // ================= phase 1: LN1 + mixes + r/k/v matvecs =============
        {
            float4 xv = __ldcg(((const float4*)g_x) + tid);
            float4 xn = ln_vec(xv, p.ln1_w + le, p.ln1_b + le, s_red);
            float4 sx = ((const float4*)(p.xx_att + le))[tid];
            float4 mr = ((const float4*)(p.mix_r + le))[tid];
            float4 mk = ((const float4*)(p.mix_k + le))[tid];
            float4 mv = ((const float4*)(p.mix_v + le))[tid];
            ((float4*)(s_buf + 0   ))[tid] = mix4(xn, sx, mr);   // xr
            ((float4*)(s_buf + E_  ))[tid] = mix4(xn, sx, mk);   // xk
            ((float4*)(s_buf + 2*E_))[tid] = mix4(xn, sx, mv);   // xv
            if (bid == 0) {
                float* o = p.out + O_XX + le + tid*4;
                o[0]=xn.x; o[1]=xn.y; o[2]=xn.z; o[3]=xn.w;
            }
            __syncthreads();
            for (unsigned idx = gwarp; idx < 3u*E_; idx += nwarp) {
                unsigned m   = idx >> 10;
                unsigned row = idx & (E_ - 1u);
                const float* wmat = (m == 0u) ? p.Wr : (m == 1u) ? p.Wk : p.Wv;
                float acc = dot_row_E(wmat + ((size_t)le + row) * E_,
                                      s_buf + m * E_, lane);
                if (lane == 0) {
                    if (m == 0u) {
                        g_rpre[row] = acc;
                        p.out[O_DA + le + row] = acc;
                        p.out[O_DB + le + row] = 1.0f / (1.0f + expf(-acc));
                    } else if (m == 1u) g_kk[row] = acc;
                    else                g_vv[row] = acc;
                }
            }
        }
        bar_t++; gsync(nb, bar_t);

        // ===== WKV elementwise (distributed producers, 32 elems each) =======
        if (bid < RABB && warp == 0) {
            int j  = (int)bid * 32 + lane;
            float kk = __ldcg(g_kk + j), vv = __ldcg(g_vv + j);
            float aa = p.aa_att[le + j], bb = p.bb_att[le + j], pp = p.pp_att[le + j];
            float tf = p.tfirst[le + j], td = p.tdecay[le + j];
            float ww = tf + kk;
            float q  = fmaxf(pp, ww);
            float e1 = expf(pp - q), e2 = expf(ww - q);
            float a  = e1 * aa + e2 * vv;
            float b  = e1 * bb + e2;
            float r  = 1.0f / (1.0f + expf(-__ldcg(g_rpre + j)));
            g_rab[j] = r * a / b;
            float ww2 = pp + td;
            float q2  = fmaxf(ww2, kk);
            float e1b = expf(ww2 - q2), e2b = expf(kk - q2);
            p.out[O_AA + le + j] = e1b * aa + e2b * vv;
            p.out[O_BB + le + j] = e1b * bb + e2b;
            p.out[O_PP + le + j] = q2;
            __threadfence();
            if (lane == 0) {
                if (atomicAdd(&g_rab_cnt, 1u) == RABB - 1u) {
                    g_rab_cnt = 0u;
                    __threadfence();
                    atomicAdd(&g_rab_gen, 1u);
                }
            }
        }
        rab_t++;
        if (tid == 0) {
            while ((int)(*(volatile unsigned*)&g_rab_gen - rab_t) < 0) __nanosleep(32);
            __threadfence();
        }
        __syncthreads();

        // ================= phase 2: x += Wo @ rab ===========================
        ((float4*)s_buf)[tid] = __ldcg(((const float4*)g_rab) + tid);
        __syncthreads();
        for (unsigned row = gwarp; row < E_; row += nwarp) {
            float acc = dot_row_E(p.Wo + ((size_t)le + row) * E_, s_buf, lane);
            if (lane == 0) g_x[row] = __ldcg(g_x + row) + acc;
        }
        bar_t++; gsync(nb, bar_t);

        // ================= phase 3: LN2 + FFN r/k matvecs ===================
        {
            float4 xv  = __ldcg(((const float4*)g_x) + tid);
            float4 xn2 = ln_vec(xv, p.ln2_w + le, p.ln2_b + le, s_red);
            float4 sxf = ((const float4*)(p.xx_ffn + le))[tid];
            float4 fk  = ((const float4*)(p.fmk + le))[tid];
            float4 fr  = ((const float4*)(p.fmr + le))[tid];
            ((float4*)(s_buf + 0 ))[tid] = mix4(xn2, sxf, fk);   // fxk
            ((float4*)(s_buf + E_))[tid] = mix4(xn2, sxf, fr);   // fxr
            if (bid == 0) {
                float* o = p.out + O_XF + le + tid*4;
                o[0]=xn2.x; o[1]=xn2.y; o[2]=xn2.z; o[3]=xn2.w;
            }
            __syncthreads();
            for (unsigned idx = gwarp; idx < (unsigned)(H_ + E_); idx += nwarp) {
                if (idx < (unsigned)H_) {
                    float acc = dot_row_E(p.Fk + ((size_t)l * H_ + idx) * E_,
                                          s_buf, lane);
                    if (lane == 0) { float t = fmaxf(acc, 0.0f); g_kf[idx] = t * t; }
                } else {
                    unsigned row = idx - (unsigned)H_;
                    float acc = dot_row_E(p.Fr + ((size_t)le + row) * E_,
                                          s_buf + E_, lane);
                    if (lane == 0) g_rfpre[row] = acc;
                }
            }
        }
        bar_t++; gsync(nb, bar_t);

        // ================= phase 4: x += sigmoid(rf) * (Fv @ kf) ============
        #pragma unroll
        for (int i = tid; i < H_/4; i += TPB)
            ((float4*)s_buf)[i] = __ldcg(((const float4*)g_kf) + i);
        __syncthreads();
        for (unsigned row = gwarp; row < E_; row += nwarp) {
            float acc = dot_row_H(p.Fv + ((size_t)le + row) * H_, s_buf, lane);
            if (lane == 0) {
                float rf = 1.0f / (1.0f + expf(-__ldcg(g_rfpre + row)));
                g_x[row] = __ldcg(g_x + row) + rf * acc;
            }
        }
        bar_t++; gsync(nb, bar_t);
    }

    // ================= head: logits = head_w @ LN(x, lno) ===================
    {
        float4 xv = __ldcg(((const float4*)g_x) + tid);
        float4 xo = ln_vec(xv, p.lno_w, p.lno_b, s_red);
        ((float4*)s_buf)[tid] = xo;
        __syncthreads();
        for (unsigned row = gwarp; row < (unsigned)V_; row += nwarp) {
            float acc = dot_row_E(p.head_w + (size_t)row * E_, s_buf, lane);
            if (lane == 0) p.out[row] = acc;
        }
    }
}

extern "C" void kernel_launch(void* const* d_in, const int* in_sizes, int n_in,
                              void* d_out, int out_size) {
    (void)in_sizes; (void)n_in; (void)out_size;
    Params p;
    p.ctx    = (const int*)  d_in[0];
    p.xx_att = (const float*)d_in[1];
    p.aa_att = (const float*)d_in[2];
    p.bb_att = (const float*)d_in[3];
    p.pp_att = (const float*)d_in[4];
    p.xx_ffn = (const float*)d_in[5];
    p.emb_w  = (const float*)d_in[6];
    p.head_w = (const float*)d_in[7];
    p.ln0_w  = (const float*)d_in[8];
    p.ln0_b  = (const float*)d_in[9];
    p.ln1_w  = (const float*)d_in[10];
    p.ln1_b  = (const float*)d_in[11];
    p.ln2_w  = (const float*)d_in[12];
    p.ln2_b  = (const float*)d_in[13];
    p.lno_w  = (const float*)d_in[14];
    p.lno_b  = (const float*)d_in[15];
    p.mix_k  = (const float*)d_in[16];
    p.mix_v  = (const float*)d_in[17];
    p.mix_r  = (const float*)d_in[18];
    p.tfirst = (const float*)d_in[19];
    p.tdecay = (const float*)d_in[20];
    p.Wr     = (const float*)d_in[21];
    p.Wk     = (const float*)d_in[22];
    p.Wv     = (const float*)d_in[23];
    p.Wo     = (const float*)d_in[24];
    p.fmk    = (const float*)d_in[25];
    p.fmr    = (const float*)d_in[26];
    p.Fr     = (const float*)d_in[27];
    p.Fk     = (const float*)d_in[28];
    p.Fv     = (const float*)d_in[29];
    p.out    = (float*)d_out;

    int dev = 0;
    cudaGetDevice(&dev);
    int sms = 0;
    cudaDeviceGetAttribute(&sms, cudaDevAttrMultiProcessorCount, dev);
    int bpm = 0;
    cudaOccupancyMaxActiveBlocksPerMultiprocessor(&bpm, rwkv_kernel, TPB, 0);
    if (bpm < 1) bpm = 1;
    if (bpm > 2) bpm = 2;          // cap: limits redundancy + barrier traffic
    unsigned nb = (unsigned)(sms * bpm);
    p.nb = nb;

    rwkv_kernel<<<nb, TPB>>>(p);
}

// round 15
// speedup vs baseline: 1.1827x; 1.1435x over previous
#include <cuda_runtime.h>
#include <cstdint>

#define E_   1024
#define L_   24
#define H_   4096
#define V_   50277
#define TPB  1024
#define WPB  32

struct Params {
    const int*   ctx;
    const float* xx_att; const float* aa_att; const float* bb_att;
    const float* pp_att; const float* xx_ffn;
    const float* emb_w;  const float* head_w;
    const float* ln0_w;  const float* ln0_b;
    const float* ln1_w;  const float* ln1_b;
    const float* ln2_w;  const float* ln2_b;
    const float* lno_w;  const float* lno_b;
    const float* mix_k;  const float* mix_v;  const float* mix_r;
    const float* tfirst; const float* tdecay;
    const float* Wr; const float* Wk; const float* Wv; const float* Wo;
    const float* fmk; const float* fmr;
    const float* Fr;  const float* Fk;  const float* Fv;
    float* out;
    unsigned nb;
};

// Cross-phase scratch (device globals: no allocations allowed)
__device__ __align__(16) float g_x[E_];
__device__ __align__(16) float g_kk[E_];
__device__ __align__(16) float g_vv[E_];
__device__ __align__(16) float g_rpre[E_];
__device__ __align__(16) float g_kf[H_];
__device__ __align__(16) float g_rfpre[E_];

// Monotonic barrier state (never reset across calls; targets are relative)
__device__ unsigned g_bar_cnt;
__device__ unsigned g_bar_gen;

__device__ __forceinline__ float warp_red(float v) {
    #pragma unroll
    for (int o = 16; o > 0; o >>= 1) v += __shfl_down_sync(0xffffffffu, v, o);
    return v;
}

// Block-wide sum across 32 warps (TPB=1024).
__device__ __forceinline__ float block_sum(float v, float* s_red) {
    int lane = threadIdx.x & 31, warp = threadIdx.x >> 5;
    v = warp_red(v);
    if (lane == 0) s_red[warp] = v;
    __syncthreads();
    if (warp == 0) {
        float t = s_red[lane];
        t = warp_red(t);
        if (lane == 0) s_red[32] = t;
    }
    __syncthreads();
    return s_red[32];
}

// Grid-wide barrier: all threads fence, tid0 arrives; last arriver resets the
// counter and bumps the generation; others spin on the generation.
__device__ __forceinline__ void gsync(unsigned nb, unsigned target) {
    __threadfence();
    __syncthreads();
    if (threadIdx.x == 0) {
        if (atomicAdd(&g_bar_cnt, 1u) == nb - 1u) {
            g_bar_cnt = 0u;
            __threadfence();
            atomicAdd(&g_bar_gen, 1u);
        } else {
            while ((int)(*(volatile unsigned*)&g_bar_gen - target) < 0) __nanosleep(32);
        }
        __threadfence();
    }
    __syncthreads();
}

// LayerNorm of a block-distributed vector: thread t holds element t (E_=TPB).
__device__ __forceinline__ float ln_scalar(float v, float w, float b, float* s_red) {
    float s = block_sum(v, s_red);
    float mean = s * (1.0f / E_);
    float c = v - mean;
    float ss = block_sum(c * c, s_red);
    float rstd = rsqrtf(ss * (1.0f / E_) + 1e-5f);
    return c * rstd * w + b;
}

// Warp dot of a 1024-long weight row (streamed, .cs) with an SMEM vector.
__device__ __forceinline__ float dot_row_E(const float* wrow, const float* vec, int lane) {
    const float4* w4 = (const float4*)wrow;
    const float4* v4 = (const float4*)vec;
    float acc = 0.0f;
    #pragma unroll
    for (int j = lane; j < E_/4; j += 32) {
        float4 a = __ldcs(w4 + j);
        float4 b = v4[j];
        acc += a.x*b.x + a.y*b.y + a.z*b.z + a.w*b.w;
    }
    return warp_red(acc);
}

// Warp dot of a 4096-long weight row with an SMEM vector.
__device__ __forceinline__ float dot_row_H(const float* wrow, const float* vec, int lane) {
    const float4* w4 = (const float4*)wrow;
    const float4* v4 = (const float4*)vec;
    float acc = 0.0f;
    #pragma unroll 8
    for (int j = lane; j < H_/4; j += 32) {
        float4 a = __ldcs(w4 + j);
        float4 b = v4[j];
        acc += a.x*b.x + a.y*b.y + a.z*b.z + a.w*b.w;
    }
    return warp_red(acc);
}

__global__ void __launch_bounds__(TPB, 1) rwkv_kernel(Params p) {
    __shared__ float s_buf[H_];   // 16KB: phase-dependent vector cache
    __shared__ float s_red[33];

    const unsigned nb   = p.nb;
    const unsigned bid  = blockIdx.x;
    const int tid  = threadIdx.x;
    const int lane = tid & 31;
    const int warp = tid >> 5;
    const unsigned gwarp = bid * WPB + (unsigned)warp;
    const unsigned nwarp = nb * WPB;

    // Barrier base sampled before any arrival (stable: gen can't bump until
    // this block arrives, and previous launch fully completed).
    unsigned bar_t = *(volatile unsigned*)&g_bar_gen;

    const unsigned O_XX = V_;
    const unsigned O_AA = V_ + 1u*L_*E_;
    const unsigned O_BB = V_ + 2u*L_*E_;
    const unsigned O_PP = V_ + 3u*L_*E_;
    const unsigned O_XF = V_ + 4u*L_*E_;
    const unsigned O_DA = V_ + 5u*L_*E_;
    const unsigned O_DB = V_ + 6u*L_*E_;

    // ---- embedding: x0 = LN(emb_w[ctx], ln0) ----
    if (bid == 0) {
        int tok = p.ctx[0];
        float ev = __ldcs(p.emb_w + (size_t)tok * E_ + tid);
        g_x[tid] = ln_scalar(ev, p.ln0_w[tid], p.ln0_b[tid], s_red);
    }
    bar_t++; gsync(nb, bar_t);

    for (int l = 0; l < L_; ++l) {
        const unsigned le = (unsigned)l * E_;

        // ================= phase 1: LN1 + mixes + r/k/v matvecs =============
        {
            float xv = __ldcg(g_x + tid);
            float xn = ln_scalar(xv, p.ln1_w[le + tid], p.ln1_b[le + tid], s_red);
            float sx = p.xx_att[le + tid];
            float mr = p.mix_r[le + tid];
            float mk = p.mix_k[le + tid];
            float mv = p.mix_v[le + tid];
            s_buf[tid       ] = xn*mr + sx*(1.0f - mr);   // xr
            s_buf[E_   + tid] = xn*mk + sx*(1.0f - mk);   // xk
            s_buf[2*E_ + tid] = xn*mv + sx*(1.0f - mv);   // xv
            if (bid == 0) p.out[O_XX + le + tid] = xn;
            __syncthreads();
            for (unsigned idx = gwarp; idx < 3u*E_; idx += nwarp) {
                unsigned m   = idx >> 10;
                unsigned row = idx & (E_ - 1u);
                const float* wmat = (m == 0u) ? p.Wr : (m == 1u) ? p.Wk : p.Wv;
                float acc = dot_row_E(wmat + ((size_t)le + row) * E_,
                                      s_buf + m * E_, lane);
                if (lane == 0) {
                    if (m == 0u) {
                        g_rpre[row] = acc;
                        p.out[O_DA + le + row] = acc;
                        p.out[O_DB + le + row] = 1.0f / (1.0f + expf(-acc));
                    } else if (m == 1u) g_kk[row] = acc;
                    else                g_vv[row] = acc;
                }
            }
        }
        bar_t++; gsync(nb, bar_t);

        // ===== WKV elementwise: every block computes all 1024 elems locally =
        {
            int j = tid;
            float kk = __ldcg(g_kk + j), vv = __ldcg(g_vv + j);
            float aa = p.aa_att[le + j], bb = p.bb_att[le + j], pp = p.pp_att[le + j];
            float tf = p.tfirst[le + j], td = p.tdecay[le + j];
            float ww = tf + kk;
            float q  = fmaxf(pp, ww);
            float e1 = expf(pp - q), e2 = expf(ww - q);
            float a  = e1 * aa + e2 * vv;
            float b  = e1 * bb + e2;
            float r  = 1.0f / (1.0f + expf(-__ldcg(g_rpre + j)));
            s_buf[j] = r * a / b;                       // rab operand for p2
            if (bid == 0) {
                float ww2 = pp + td;
                float q2  = fmaxf(ww2, kk);
                float e1b = expf(ww2 - q2), e2b = expf(kk - q2);
                p.out[O_AA + le + j] = e1b * aa + e2b * vv;
                p.out[O_BB + le + j] = e1b * bb + e2b;
                p.out[O_PP + le + j] = q2;
            }
        }
        __syncthreads();

        // ================= phase 2: x += Wo @ rab ===========================
        for (unsigned row = gwarp; row < E_; row += nwarp) {
            float acc = dot_row_E(p.Wo + ((size_t)le + row) * E_, s_buf, lane);
            if (lane == 0) g_x[row] = __ldcg(g_x + row) + acc;
        }
        bar_t++; gsync(nb, bar_t);

        // ================= phase 3: LN2 + FFN r/k matvecs ===================
        {
            float xv  = __ldcg(g_x + tid);
            float xn2 = ln_scalar(xv, p.ln2_w[le + tid], p.ln2_b[le + tid], s_red);
            float sxf = p.xx_ffn[le + tid];
            float fk  = p.fmk[le + tid];
            float fr  = p.fmr[le + tid];
            s_buf[tid     ] = xn2*fk + sxf*(1.0f - fk);   // fxk
            s_buf[E_ + tid] = xn2*fr + sxf*(1.0f - fr);   // fxr
            if (bid == 0) p.out[O_XF + le + tid] = xn2;
            __syncthreads();
            for (unsigned idx = gwarp; idx < (unsigned)(H_ + E_); idx += nwarp) {
                if (idx < (unsigned)H_) {
                    float acc = dot_row_E(p.Fk + ((size_t)l * H_ + idx) * E_,
                                          s_buf, lane);
                    if (lane == 0) { float t = fmaxf(acc, 0.0f); g_kf[idx] = t * t; }
                } else {
                    unsigned row = idx - (unsigned)H_;
                    float acc = dot_row_E(p.Fr + ((size_t)le + row) * E_,
                                          s_buf + E_, lane);
                    if (lane == 0) g_rfpre[row] = acc;
                }
            }
        }
        bar_t++; gsync(nb, bar_t);

        // ================= phase 4: x += sigmoid(rf) * (Fv @ kf) ============
        #pragma unroll
        for (int i = tid; i < H_/4; i += TPB)
            ((float4*)s_buf)[i] = __ldcg(((const float4*)g_kf) + i);
        __syncthreads();
        for (unsigned row = gwarp; row < E_; row += nwarp) {
            float acc = dot_row_H(p.Fv + ((size_t)le + row) * H_, s_buf, lane);
            if (lane == 0) {
                float rf = 1.0f / (1.0f + expf(-__ldcg(g_rfpre + row)));
                g_x[row] = __ldcg(g_x + row) + rf * acc;
            }
        }
        bar_t++; gsync(nb, bar_t);
    }

    // ================= head: logits = head_w @ LN(x, lno) ===================
    {
        float xv = __ldcg(g_x + tid);
        float xo = ln_scalar(xv, p.lno_w[tid], p.lno_b[tid], s_red);
        s_buf[tid] = xo;
        __syncthreads();
        for (unsigned row = gwarp; row < (unsigned)V_; row += nwarp) {
            float acc = dot_row_E(p.head_w + (size_t)row * E_, s_buf, lane);
            if (lane == 0) p.out[row] = acc;
        }
    }
}

extern "C" void kernel_launch(void* const* d_in, const int* in_sizes, int n_in,
                              void* d_out, int out_size) {
    (void)in_sizes; (void)n_in; (void)out_size;
    Params p;
    p.ctx    = (const int*)  d_in[0];
    p.xx_att = (const float*)d_in[1];
    p.aa_att = (const float*)d_in[2];
    p.bb_att = (const float*)d_in[3];
    p.pp_att = (const float*)d_in[4];
    p.xx_ffn = (const float*)d_in[5];
    p.emb_w  = (const float*)d_in[6];
    p.head_w = (const float*)d_in[7];
    p.ln0_w  = (const float*)d_in[8];
    p.ln0_b  = (const float*)d_in[9];
    p.ln1_w  = (const float*)d_in[10];
    p.ln1_b  = (const float*)d_in[11];
    p.ln2_w  = (const float*)d_in[12];
    p.ln2_b  = (const float*)d_in[13];
    p.lno_w  = (const float*)d_in[14];
    p.lno_b  = (const float*)d_in[15];
    p.mix_k  = (const float*)d_in[16];
    p.mix_v  = (const float*)d_in[17];
    p.mix_r  = (const float*)d_in[18];
    p.tfirst = (const float*)d_in[19];
    p.tdecay = (const float*)d_in[20];
    p.Wr     = (const float*)d_in[21];
    p.Wk     = (const float*)d_in[22];
    p.Wv     = (const float*)d_in[23];
    p.Wo     = (const float*)d_in[24];
    p.fmk    = (const float*)d_in[25];
    p.fmr    = (const float*)d_in[26];
    p.Fr     = (const float*)d_in[27];
    p.Fk     = (const float*)d_in[28];
    p.Fv     = (const float*)d_in[29];
    p.out    = (float*)d_out;

    int dev = 0;
    cudaGetDevice(&dev);
    int sms = 0;
    cudaDeviceGetAttribute(&sms, cudaDevAttrMultiProcessorCount, dev);
    unsigned nb = (unsigned)sms;   // 1 block/SM, guaranteed co-resident
    p.nb = nb;

    rwkv_kernel<<<nb, TPB>>>(p);
}

// round 16
// speedup vs baseline: 1.4066x; 1.1892x over previous
#include <cuda_runtime.h>
#include <cstdint>

#define E_   1024
#define L_   24
#define H_   4096
#define V_   50277
#define TPB  1024
#define WPB  32

struct Params {
    const int*   ctx;
    const float* xx_att; const float* aa_att; const float* bb_att;
    const float* pp_att; const float* xx_ffn;
    const float* emb_w;  const float* head_w;
    const float* ln0_w;  const float* ln0_b;
    const float* ln1_w;  const float* ln1_b;
    const float* ln2_w;  const float* ln2_b;
    const float* lno_w;  const float* lno_b;
    const float* mix_k;  const float* mix_v;  const float* mix_r;
    const float* tfirst; const float* tdecay;
    const float* Wr; const float* Wk; const float* Wv; const float* Wo;
    const float* fmk; const float* fmr;
    const float* Fr;  const float* Fk;  const float* Fv;
    float* out;
    unsigned nb;
};

// Cross-phase scratch (device globals: no allocations allowed)
__device__ __align__(16) float g_x[E_];
__device__ __align__(16) float g_kk[E_];
__device__ __align__(16) float g_vv[E_];
__device__ __align__(16) float g_rpre[E_];
__device__ __align__(16) float g_kf[H_];
__device__ __align__(16) float g_rfpre[E_];

// Monotonic barrier state (never reset across calls; targets are relative)
__device__ unsigned g_bar_cnt;
__device__ unsigned g_bar_gen;

__device__ __forceinline__ float warp_red(float v) {
    #pragma unroll
    for (int o = 16; o > 0; o >>= 1) v += __shfl_down_sync(0xffffffffu, v, o);
    return v;
}

// Block-wide sum across 32 warps (TPB=1024).
__device__ __forceinline__ float block_sum(float v, float* s_red) {
    int lane = threadIdx.x & 31, warp = threadIdx.x >> 5;
    v = warp_red(v);
    if (lane == 0) s_red[warp] = v;
    __syncthreads();
    if (warp == 0) {
        float t = s_red[lane];
        t = warp_red(t);
        if (lane == 0) s_red[32] = t;
    }
    __syncthreads();
    return s_red[32];
}

// Grid-wide barrier: all threads fence, tid0 arrives; last arriver resets the
// counter and bumps the generation; others spin on the generation.
__device__ __forceinline__ void gsync(unsigned nb, unsigned target) {
    __threadfence();
    __syncthreads();
    if (threadIdx.x == 0) {
        if (atomicAdd(&g_bar_cnt, 1u) == nb - 1u) {
            g_bar_cnt = 0u;
            __threadfence();
            atomicAdd(&g_bar_gen, 1u);
        } else {
            while ((int)(*(volatile unsigned*)&g_bar_gen - target) < 0) __nanosleep(32);
        }
        __threadfence();
    }
    __syncthreads();
}

// LayerNorm of a block-distributed vector: thread t holds element t (E_=TPB).
__device__ __forceinline__ float ln_scalar(float v, float w, float b, float* s_red) {
    float s = block_sum(v, s_red);
    float mean = s * (1.0f / E_);
    float c = v - mean;
    float ss = block_sum(c * c, s_red);
    float rstd = rsqrtf(ss * (1.0f / E_) + 1e-5f);
    return c * rstd * w + b;
}

// Warp dot of a 1024-long weight row (streamed, .cs) with an SMEM vector.
__device__ __forceinline__ float dot_row_E(const float* wrow, const float* vec, int lane) {
    const float4* w4 = (const float4*)wrow;
    const float4* v4 = (const float4*)vec;
    float acc = 0.0f;
    #pragma unroll
    for (int j = lane; j < E_/4; j += 32) {
        float4 a = __ldcs(w4 + j);
        float4 b = v4[j];
        acc += a.x*b.x + a.y*b.y + a.z*b.z + a.w*b.w;
    }
    return warp_red(acc);
}

// Warp dot of a 4096-long weight row with an SMEM vector.
__device__ __forceinline__ float dot_row_H(const float* wrow, const float* vec, int lane) {
    const float4* w4 = (const float4*)wrow;
    const float4* v4 = (const float4*)vec;
    float acc = 0.0f;
    #pragma unroll 8
    for (int j = lane; j < H_/4; j += 32) {
        float4 a = __ldcs(w4 + j);
        float4 b = v4[j];
        acc += a.x*b.x + a.y*b.y + a.z*b.z + a.w*b.w;
    }
    return warp_red(acc);
}

__global__ void __launch_bounds__(TPB, 1) rwkv_kernel(Params p) {
    __shared__ float s_buf[H_];   // 16KB: phase-dependent vector cache
    __shared__ float s_red[33];

    const unsigned nb   = p.nb;
    const unsigned bid  = blockIdx.x;
    const int tid  = threadIdx.x;
    const int lane = tid & 31;
    const int warp = tid >> 5;
    const unsigned gwarp = bid * WPB + (unsigned)warp;
    const unsigned nwarp = nb * WPB;

    // Barrier base sampled before any arrival (stable: gen can't bump until
    // this block arrives, and previous launch fully completed).
    unsigned bar_t = *(volatile unsigned*)&g_bar_gen;

    const unsigned O_XX = V_;
    const unsigned O_AA = V_ + 1u*L_*E_;
    const unsigned O_BB = V_ + 2u*L_*E_;
    const unsigned O_PP = V_ + 3u*L_*E_;
    const unsigned O_XF = V_ + 4u*L_*E_;
    const unsigned O_DA = V_ + 5u*L_*E_;
    const unsigned O_DB = V_ + 6u*L_*E_;

    // ---- embedding: x0 = LN(emb_w[ctx], ln0) ----
    if (bid == 0) {
        int tok = p.ctx[0];
        float ev = __ldcs(p.emb_w + (size_t)tok * E_ + tid);
        g_x[tid] = ln_scalar(ev, p.ln0_w[tid], p.ln0_b[tid], s_red);
    }
    bar_t++; gsync(nb, bar_t);

    for (int l = 0; l < L_; ++l) {
        const unsigned le = (unsigned)l * E_;

        // ================= phase 1: LN1 + mixes + r/k/v matvecs =============
        {
            float xv = __ldcg(g_x + tid);
            float xn = ln_scalar(xv, p.ln1_w[le + tid], p.ln1_b[le + tid], s_red);
            float sx = p.xx_att[le + tid];
            float mr = p.mix_r[le + tid];
            float mk = p.mix_k[le + tid];
            float mv = p.mix_v[le + tid];
            s_buf[tid       ] = xn*mr + sx*(1.0f - mr);   // xr
            s_buf[E_   + tid] = xn*mk + sx*(1.0f - mk);   // xk
            s_buf[2*E_ + tid] = xn*mv + sx*(1.0f - mv);   // xv
            if (bid == 0) p.out[O_XX + le + tid] = xn;
            __syncthreads();
            for (unsigned idx = gwarp; idx < 3u*E_; idx += nwarp) {
                unsigned m   = idx >> 10;
                unsigned row = idx & (E_ - 1u);
                const float* wmat = (m == 0u) ? p.Wr : (m == 1u) ? p.Wk : p.Wv;
                float acc = dot_row_E(wmat + ((size_t)le + row) * E_,
                                      s_buf + m * E_, lane);
                if (lane == 0) {
                    if (m == 0u) {
                        g_rpre[row] = acc;
                        p.out[O_DA + le + row] = acc;
                        p.out[O_DB + le + row] = 1.0f / (1.0f + expf(-acc));
                    } else if (m == 1u) g_kk[row] = acc;
                    else                g_vv[row] = acc;
                }
            }
        }
        bar_t++; gsync(nb, bar_t);

        // ===== WKV elementwise: every block computes all 1024 elems locally =
        {
            int j = tid;
            float kk = __ldcg(g_kk + j), vv = __ldcg(g_vv + j);
            float aa = p.aa_att[le + j], bb = p.bb_att[le + j], pp = p.pp_att[le + j];
            float tf = p.tfirst[le + j], td = p.tdecay[le + j];
            float ww = tf + kk;
            float q  = fmaxf(pp, ww);
            float e1 = expf(pp - q), e2 = expf(ww - q);
            float a  = e1 * aa + e2 * vv;
            float b  = e1 * bb + e2;
            float r  = 1.0f / (1.0f + expf(-__ldcg(g_rpre + j)));
            s_buf[j] = r * a / b;                       // rab operand for p2
            if (bid == 0) {
                float ww2 = pp + td;
                float q2  = fmaxf(ww2, kk);
                float e1b = expf(ww2 - q2), e2b = expf(kk - q2);
                p.out[O_AA + le + j] = e1b * aa + e2b * vv;
                p.out[O_BB + le + j] = e1b * bb + e2b;
                p.out[O_PP + le + j] = q2;
            }
        }
        __syncthreads();

        // ================= phase 2: x += Wo @ rab ===========================
        for (unsigned row = gwarp; row < E_; row += nwarp) {
            float acc = dot_row_E(p.Wo + ((size_t)le + row) * E_, s_buf, lane);
            if (lane == 0) g_x[row] = __ldcg(g_x + row) + acc;
        }
        bar_t++; gsync(nb, bar_t);

        // ================= phase 3: LN2 + FFN r/k matvecs ===================
        {
            float xv  = __ldcg(g_x + tid);
            float xn2 = ln_scalar(xv, p.ln2_w[le + tid], p.ln2_b[le + tid], s_red);
            float sxf = p.xx_ffn[le + tid];
            float fk  = p.fmk[le + tid];
            float fr  = p.fmr[le + tid];
            s_buf[tid     ] = xn2*fk + sxf*(1.0f - fk);   // fxk
            s_buf[E_ + tid] = xn2*fr + sxf*(1.0f - fr);   // fxr
            if (bid == 0) p.out[O_XF + le + tid] = xn2;
            __syncthreads();
            for (unsigned idx = gwarp; idx < (unsigned)(H_ + E_); idx += nwarp) {
                if (idx < (unsigned)H_) {
                    float acc = dot_row_E(p.Fk + ((size_t)l * H_ + idx) * E_,
                                          s_buf, lane);
                    if (lane == 0) { float t = fmaxf(acc, 0.0f); g_kf[idx] = t * t; }
                } else {
                    unsigned row = idx - (unsigned)H_;
                    float acc = dot_row_E(p.Fr + ((size_t)le + row) * E_,
                                          s_buf + E_, lane);
                    if (lane == 0) g_rfpre[row] = acc;
                }
            }
        }
        bar_t++; gsync(nb, bar_t);

        // ================= phase 4: x += sigmoid(rf) * (Fv @ kf) ============
        #pragma unroll
        for (int i = tid; i < H_/4; i += TPB)
            ((float4*)s_buf)[i] = __ldcg(((const float4*)g_kf) + i);
        __syncthreads();
        for (unsigned row = gwarp; row < E_; row += nwarp) {
            float acc = dot_row_H(p.Fv + ((size_t)le + row) * H_, s_buf, lane);
            if (lane == 0) {
                float rf = 1.0f / (1.0f + expf(-__ldcg(g_rfpre + row)));
                g_x[row] = __ldcg(g_x + row) + rf * acc;
            }
        }
        bar_t++; gsync(nb, bar_t);
    }

    // ================= head: logits = head_w @ LN(x, lno) ===================
    {
        float xv = __ldcg(g_x + tid);
        float xo = ln_scalar(xv, p.lno_w[tid], p.lno_b[tid], s_red);
        s_buf[tid] = xo;
        __syncthreads();
        for (unsigned row = gwarp; row < (unsigned)V_; row += nwarp) {
            float acc = dot_row_E(p.head_w + (size_t)row * E_, s_buf, lane);
            if (lane == 0) p.out[row] = acc;
        }
    }
}

extern "C" void kernel_launch(void* const* d_in, const int* in_sizes, int n_in,
                              void* d_out, int out_size) {
    (void)in_sizes; (void)n_in; (void)out_size;
    Params p;
    p.ctx    = (const int*)  d_in[0];
    p.xx_att = (const float*)d_in[1];
    p.aa_att = (const float*)d_in[2];
    p.bb_att = (const float*)d_in[3];
    p.pp_att = (const float*)d_in[4];
    p.xx_ffn = (const float*)d_in[5];
    p.emb_w  = (const float*)d_in[6];
    p.head_w = (const float*)d_in[7];
    p.ln0_w  = (const float*)d_in[8];
    p.ln0_b  = (const float*)d_in[9];
    p.ln1_w  = (const float*)d_in[10];
    p.ln1_b  = (const float*)d_in[11];
    p.ln2_w  = (const float*)d_in[12];
    p.ln2_b  = (const float*)d_in[13];
    p.lno_w  = (const float*)d_in[14];
    p.lno_b  = (const float*)d_in[15];
    p.mix_k  = (const float*)d_in[16];
    p.mix_v  = (const float*)d_in[17];
    p.mix_r  = (const float*)d_in[18];
    p.tfirst = (const float*)d_in[19];
    p.tdecay = (const float*)d_in[20];
    p.Wr     = (const float*)d_in[21];
    p.Wk     = (const float*)d_in[22];
    p.Wv     = (const float*)d_in[23];
    p.Wo     = (const float*)d_in[24];
    p.fmk    = (const float*)d_in[25];
    p.fmr    = (const float*)d_in[26];
    p.Fr     = (const float*)d_in[27];
    p.Fk     = (const float*)d_in[28];
    p.Fv     = (const float*)d_in[29];
    p.out    = (float*)d_out;

    int dev = 0;
    cudaGetDevice(&dev);
    int sms = 0;
    cudaDeviceGetAttribute(&sms, cudaDevAttrMultiProcessorCount, dev);
    unsigned nb = (unsigned)sms;   // 1 block/SM, guaranteed co-resident
    p.nb = nb;

    rwkv_kernel<<<nb, TPB>>>(p);
}